// round 1
// baseline (speedup 1.0000x reference)
#include <cuda_runtime.h>
#include <cuda_bf16.h>
#include <math.h>

#define B_   32
#define NN   511
#define F_   512
#define F3   1536
#define NP   255   // internal nodes (parents)

// ---------------- scratch (static device memory; no allocations) ----------------
__device__ __align__(16) float g_enode [B_*F_];
__device__ __align__(16) float g_eforw [B_*F_];
__device__ __align__(16) float g_scores[B_*NN];
__device__ __align__(16) float g_logits[B_*NN];
__device__ __align__(16) float g_feat2 [B_*NN*F_];
__device__ __align__(16) float g_feiou [(size_t)B_*NN*F3];
__device__ __align__(16) float g_fefp  [B_*NP*F_];
__device__ __align__(16) float g_h     [B_*NN*F_];
__device__ __align__(16) float g_c     [B_*NN*F_];
__device__ __align__(16) float g_iou_t [B_*128*F3];
__device__ __align__(16) float g_f_t   [B_*256*F_];

__device__ __forceinline__ float sigm(float x) { return 1.f / (1.f + expf(-x)); }

// ---------------- e_node / e_forw projection: warp per output ----------------
__global__ void eh_proj_kernel(const float* __restrict__ eh, const float* __restrict__ Wn,
                               const float* __restrict__ Wf, float* __restrict__ en,
                               float* __restrict__ ef) {
    int gw   = (blockIdx.x * blockDim.x + threadIdx.x) >> 5;
    int lane = threadIdx.x & 31;
    if (gw >= 2 * B_ * F_) return;
    int which = (gw >= B_ * F_);
    int rem   = which ? gw - B_ * F_ : gw;
    int b = rem >> 9, f = rem & 511;
    const float4* w4 = (const float4*)((which ? Wf : Wn) + (size_t)f * 1024);
    const float4* e4 = (const float4*)(eh + (size_t)b * 1024);
    float s = 0.f;
    for (int k = lane; k < 256; k += 32) {
        float4 a = w4[k], c = e4[k];
        s += a.x * c.x + a.y * c.y + a.z * c.z + a.w * c.w;
    }
    #pragma unroll
    for (int o = 16; o; o >>= 1) s += __shfl_down_sync(0xffffffffu, s, o);
    if (!lane) (which ? ef : en)[rem] = s;
}

// ---------------- dot of each (b,node) row with a per-batch vector ----------------
__global__ void dot_kernel(const float* __restrict__ X, const float* __restrict__ v,
                           float* __restrict__ out) {
    int gw   = (blockIdx.x * blockDim.x + threadIdx.x) >> 5;
    int lane = threadIdx.x & 31;
    if (gw >= B_ * NN) return;
    int b = gw / NN;
    const float4* x4 = (const float4*)(X + (size_t)gw * F_);
    const float4* v4 = (const float4*)(v + (size_t)b * F_);
    float s = 0.f;
    #pragma unroll
    for (int k = lane; k < 128; k += 32) {
        float4 a = x4[k], c = v4[k];
        s += a.x * c.x + a.y * c.y + a.z * c.z + a.w * c.w;
    }
    #pragma unroll
    for (int o = 16; o; o >>= 1) s += __shfl_down_sync(0xffffffffu, s, o);
    if (!lane) out[gw] = s;
}

// ---------------- windowed softmax attention -> feat2 ----------------
__global__ void feat2_kernel(const float* __restrict__ feat, const float* __restrict__ scores,
                             float* __restrict__ feat2) {
    int bi = blockIdx.x;           // = b*NN + i
    int b = bi / NN, i = bi % NN;
    int cnt = min(i + 3, NN - 1) - i + 1;
    float w[4];
    float mx = -1e30f;
    for (int j = 0; j < cnt; j++) { w[j] = scores[b * NN + i + j]; mx = fmaxf(mx, w[j]); }
    float s = 0.f;
    for (int j = 0; j < cnt; j++) { w[j] = expf(w[j] - mx); s += w[j]; }
    float inv = 1.f / s;
    const float* base = feat + (size_t)bi * F_;
    float* o = feat2 + (size_t)bi * F_;
    for (int f = threadIdx.x; f < F_; f += 256) {
        float a = 0.f;
        for (int j = 0; j < cnt; j++) a += w[j] * base[(size_t)j * F_ + f];
        o[f] = a * inv;
    }
}

// ---------------- SGEMM: C[M,N] = gather(A)[M,K] @ B[N,K]^T (+bias) ----------------
// MODE 0: A row m  = A + m*K                        (plain, contiguous)
// MODE 1: b=m/cnt, p=nodeStart+m%cnt; row = A + b*batchStride + p*K      (gather)
// MODE 2: like 1 but row = h[2p+1] + h[2p+2]        (children-sum gather)
template <int MODE>
__global__ __launch_bounds__(256, 2)
void gemm_kernel(const float* __restrict__ A, const float* __restrict__ Bm,
                 const float* __restrict__ bias, float* __restrict__ C,
                 int M, int N, int K, int nodeStart, int cnt, int batchStride) {
    __shared__ float As[16][132];
    __shared__ float Bs[16][132];
    const int tid   = threadIdx.x;
    const int tileM = blockIdx.y * 128;
    const int tileN = blockIdx.x * 128;
    const int tx = tid & 15, ty = tid >> 4;
    const int lr = tid >> 2;          // 0..63
    const int lc = (tid & 3) * 4;     // 0,4,8,12

    const float* ap[2];
    const float* ap2[2];
    bool av[2];
    #pragma unroll
    for (int p = 0; p < 2; p++) {
        int gm = tileM + lr + p * 64;
        av[p] = (gm < M);
        int g = av[p] ? gm : 0;
        if (MODE == 0) {
            ap[p] = A + (size_t)g * K;
            ap2[p] = ap[p];
        } else {
            int b = g / cnt;
            int node = nodeStart + g % cnt;
            if (MODE == 1) {
                ap[p] = A + (size_t)b * batchStride + (size_t)node * K;
                ap2[p] = ap[p];
            } else {
                ap[p]  = A + (size_t)b * batchStride + (size_t)(2 * node + 1) * K;
                ap2[p] = A + (size_t)b * batchStride + (size_t)(2 * node + 2) * K;
            }
        }
    }
    const float* bp0 = Bm + (size_t)(tileN + lr) * K;
    const float* bp1 = Bm + (size_t)(tileN + lr + 64) * K;

    float acc[8][8] = {};

    for (int k0 = 0; k0 < K; k0 += 16) {
        #pragma unroll
        for (int p = 0; p < 2; p++) {
            float4 v = make_float4(0.f, 0.f, 0.f, 0.f);
            if (av[p]) {
                v = *reinterpret_cast<const float4*>(ap[p] + k0 + lc);
                if (MODE == 2) {
                    float4 v2 = *reinterpret_cast<const float4*>(ap2[p] + k0 + lc);
                    v.x += v2.x; v.y += v2.y; v.z += v2.z; v.w += v2.w;
                }
            }
            int m = lr + p * 64;
            As[lc + 0][m] = v.x; As[lc + 1][m] = v.y;
            As[lc + 2][m] = v.z; As[lc + 3][m] = v.w;
        }
        {
            float4 v = *reinterpret_cast<const float4*>(bp0 + k0 + lc);
            Bs[lc + 0][lr] = v.x; Bs[lc + 1][lr] = v.y;
            Bs[lc + 2][lr] = v.z; Bs[lc + 3][lr] = v.w;
            v = *reinterpret_cast<const float4*>(bp1 + k0 + lc);
            Bs[lc + 0][lr + 64] = v.x; Bs[lc + 1][lr + 64] = v.y;
            Bs[lc + 2][lr + 64] = v.z; Bs[lc + 3][lr + 64] = v.w;
        }
        __syncthreads();
        #pragma unroll
        for (int kk = 0; kk < 16; kk++) {
            float a[8], bb[8];
            float4 t0 = *reinterpret_cast<const float4*>(&As[kk][ty * 8]);
            float4 t1 = *reinterpret_cast<const float4*>(&As[kk][ty * 8 + 4]);
            a[0]=t0.x; a[1]=t0.y; a[2]=t0.z; a[3]=t0.w;
            a[4]=t1.x; a[5]=t1.y; a[6]=t1.z; a[7]=t1.w;
            float4 u0 = *reinterpret_cast<const float4*>(&Bs[kk][tx * 8]);
            float4 u1 = *reinterpret_cast<const float4*>(&Bs[kk][tx * 8 + 4]);
            bb[0]=u0.x; bb[1]=u0.y; bb[2]=u0.z; bb[3]=u0.w;
            bb[4]=u1.x; bb[5]=u1.y; bb[6]=u1.z; bb[7]=u1.w;
            #pragma unroll
            for (int i = 0; i < 8; i++)
                #pragma unroll
                for (int j = 0; j < 8; j++)
                    acc[i][j] += a[i] * bb[j];
        }
        __syncthreads();
    }

    #pragma unroll
    for (int i = 0; i < 8; i++) {
        int gm = tileM + ty * 8 + i;
        if (gm >= M) continue;
        float* crow = C + (size_t)gm * N + tileN + tx * 8;
        #pragma unroll
        for (int j = 0; j < 8; j++) {
            float v = acc[i][j];
            if (bias) v += bias[tileN + tx * 8 + j];
            crow[j] = v;
        }
    }
}

// ---------------- leaves (order 0): nodes 255..510 ----------------
__global__ void leaf_kernel(const float* __restrict__ feiou, float* __restrict__ h,
                            float* __restrict__ c) {
    size_t idx = (size_t)blockIdx.x * blockDim.x + threadIdx.x;
    if (idx >= (size_t)B_ * 256 * F_) return;
    int f = idx & (F_ - 1);
    size_t t = idx >> 9;
    int node = 255 + (int)(t % 256);
    int b = (int)(t / 256);
    size_t row = (size_t)b * NN + node;
    const float* r = feiou + row * F3;
    float ig = r[f], og = r[512 + f], ug = r[1024 + f];
    float cn = sigm(ig) * fmaxf(ug, 0.f);
    float hn = sigm(og) * tanhf(cn);
    c[row * F_ + f] = cn;
    h[row * F_ + f] = hn;
}

// ---------------- per-level combine / gate update ----------------
__global__ void combine_kernel(const float* __restrict__ iou_t, const float* __restrict__ f_t,
                               const float* __restrict__ feiou, const float* __restrict__ fefp,
                               float* __restrict__ h, float* __restrict__ c,
                               int start, int cnt) {
    size_t idx = (size_t)blockIdx.x * blockDim.x + threadIdx.x;
    if (idx >= (size_t)B_ * cnt * F_) return;
    int f = idx & (F_ - 1);
    size_t t = idx >> 9;
    int q = (int)(t % cnt);
    int b = (int)(t / cnt);
    int p = start + q;
    size_t r    = (size_t)b * cnt + q;
    size_t prow = (size_t)b * NN + p;
    const float* it = iou_t + r * F3;
    const float* fi = feiou + prow * F3;
    float ig = it[f]        + fi[f];
    float og = it[512 + f]  + fi[512 + f];
    float ug = it[1024 + f] + fi[1024 + f];
    float fe = fefp[((size_t)b * NP + p) * F_ + f];
    size_t rf = ((size_t)b * 2 * cnt + 2 * q) * F_ + f;
    float fL = sigm(f_t[rf]       + fe);
    float fR = sigm(f_t[rf + F_]  + fe);
    size_t cl = ((size_t)b * NN + 2 * p + 1) * F_ + f;
    float csum = fL * c[cl] + fR * c[cl + F_];
    float cn = sigm(ig) * fmaxf(ug, 0.f) + csum;
    float hn = sigm(og) * tanhf(cn);
    c[prow * F_ + f] = cn;
    h[prow * F_ + f] = hn;
}

// ---------------- final: softmax over nodes, weighted sum of h ----------------
__global__ void final_kernel(const float* __restrict__ logits, const float* __restrict__ h,
                             float* __restrict__ out) {
    int b = blockIdx.x;
    int t = threadIdx.x;  // 512 threads; t is also the feature index
    __shared__ float sp[512];
    __shared__ float red[17];
    float l = (t < NN) ? logits[b * NN + t] : -1e30f;
    float m = l;
    #pragma unroll
    for (int o = 16; o; o >>= 1) m = fmaxf(m, __shfl_xor_sync(0xffffffffu, m, o));
    if ((t & 31) == 0) red[t >> 5] = m;
    __syncthreads();
    if (t == 0) {
        float mm = red[0];
        for (int i = 1; i < 16; i++) mm = fmaxf(mm, red[i]);
        red[16] = mm;
    }
    __syncthreads();
    float mx = red[16];
    float e = (t < NN) ? expf(l - mx) : 0.f;
    sp[t] = e;
    float s = e;
    #pragma unroll
    for (int o = 16; o; o >>= 1) s += __shfl_xor_sync(0xffffffffu, s, o);
    __syncthreads();
    if ((t & 31) == 0) red[t >> 5] = s;
    __syncthreads();
    if (t == 0) {
        float ss = 0.f;
        for (int i = 0; i < 16; i++) ss += red[i];
        red[16] = 1.f / ss;
    }
    __syncthreads();
    float inv = red[16];
    const float* hb = h + (size_t)b * NN * F_;
    float acc = 0.f;
    for (int i = 0; i < NN; i++) acc += sp[i] * hb[(size_t)i * F_ + t];
    out[b * F_ + t] = acc * inv;
}

// ---------------- launch ----------------
extern "C" void kernel_launch(void* const* d_in, const int* in_sizes, int n_in,
                              void* d_out, int out_size) {
    const float* features   = (const float*)d_in[0];
    const float* eh         = (const float*)d_in[5];
    const float* Wn         = (const float*)d_in[6];
    const float* Wf         = (const float*)d_in[7];
    const float* W_U_iou    = (const float*)d_in[8];
    const float* W_U_fe_iou = (const float*)d_in[9];
    const float* b_U_fe_iou = (const float*)d_in[10];
    const float* W_U_f      = (const float*)d_in[11];
    const float* W_U_fe_f   = (const float*)d_in[12];
    const float* b_U_fe_f   = (const float*)d_in[13];
    float* out = (float*)d_out;

    float *p_en, *p_ef, *p_sc, *p_lg, *p_feat2, *p_feiou, *p_fefp, *p_h, *p_c, *p_iou, *p_f;
    cudaGetSymbolAddress((void**)&p_en,    g_enode);
    cudaGetSymbolAddress((void**)&p_ef,    g_eforw);
    cudaGetSymbolAddress((void**)&p_sc,    g_scores);
    cudaGetSymbolAddress((void**)&p_lg,    g_logits);
    cudaGetSymbolAddress((void**)&p_feat2, g_feat2);
    cudaGetSymbolAddress((void**)&p_feiou, g_feiou);
    cudaGetSymbolAddress((void**)&p_fefp,  g_fefp);
    cudaGetSymbolAddress((void**)&p_h,     g_h);
    cudaGetSymbolAddress((void**)&p_c,     g_c);
    cudaGetSymbolAddress((void**)&p_iou,   g_iou_t);
    cudaGetSymbolAddress((void**)&p_f,     g_f_t);

    // 1) eh projections
    eh_proj_kernel<<<(2 * B_ * F_ * 32 + 255) / 256, 256>>>(eh, Wn, Wf, p_en, p_ef);
    // 2) attention scores + windowed softmax pooling
    dot_kernel<<<(B_ * NN * 32 + 255) / 256, 256>>>(features, p_en, p_sc);
    feat2_kernel<<<B_ * NN, 256>>>(features, p_sc, p_feat2);
    // 3) fe_iou (big GEMM) and per-parent fe_f
    {
        dim3 g(F3 / 128, (B_ * NN + 127) / 128);
        gemm_kernel<0><<<g, 256>>>(p_feat2, W_U_fe_iou, b_U_fe_iou, p_feiou,
                                   B_ * NN, F3, F_, 0, 0, 0);
    }
    {
        dim3 g(F_ / 128, (B_ * NP + 127) / 128);
        gemm_kernel<1><<<g, 256>>>(p_feat2, W_U_fe_f, b_U_fe_f, p_fefp,
                                   B_ * NP, F_, F_, 0, NP, NN * F_);
    }
    // 4) leaves
    leaf_kernel<<<(B_ * 256 * F_) / 256, 256>>>(p_feiou, p_h, p_c);
    // 5) levels bottom-up (n = 1..8, depth 8-n)
    for (int n = 1; n <= 8; n++) {
        int cnt = 1 << (8 - n);     // parents at this level per batch
        int start = cnt - 1;        // first parent node id
        dim3 g1(F3 / 128, (B_ * cnt + 127) / 128);
        gemm_kernel<2><<<g1, 256>>>(p_h, W_U_iou, nullptr, p_iou,
                                    B_ * cnt, F3, F_, start, cnt, NN * F_);
        dim3 g2(F_ / 128, (B_ * 2 * cnt + 127) / 128);
        gemm_kernel<1><<<g2, 256>>>(p_h, W_U_f, nullptr, p_f,
                                    B_ * 2 * cnt, F_, F_, 2 * start + 1, 2 * cnt, NN * F_);
        combine_kernel<<<(B_ * cnt * F_ + 255) / 256, 256>>>(p_iou, p_f, p_feiou, p_fefp,
                                                             p_h, p_c, start, cnt);
    }
    // 6) output pooling
    dot_kernel<<<(B_ * NN * 32 + 255) / 256, 256>>>(p_h, p_ef, p_lg);
    final_kernel<<<B_, F_>>>(p_lg, p_h, out);
}

// round 2
// speedup vs baseline: 1.2416x; 1.2416x over previous
#include <cuda_runtime.h>
#include <cuda_bf16.h>
#include <math.h>

#define B_   32
#define NN   511
#define F_   512
#define F3   1536
#define NP   255   // internal nodes (parents)

// ---------------- scratch (static device memory; no allocations) ----------------
__device__ __align__(16) float g_enode [B_*F_];
__device__ __align__(16) float g_eforw [B_*F_];
__device__ __align__(16) float g_scores[B_*NN];
__device__ __align__(16) float g_logits[B_*NN];
__device__ __align__(16) float g_feat2 [B_*NN*F_];
__device__ __align__(16) float g_feiou [(size_t)B_*NN*F3];
__device__ __align__(16) float g_fefp  [B_*NP*F_];
__device__ __align__(16) float g_h     [B_*NN*F_];
__device__ __align__(16) float g_c     [B_*NN*F_];
__device__ __align__(16) float g_iou_t [B_*128*F3];
__device__ __align__(16) float g_f_t   [B_*256*F_];

__device__ __forceinline__ float sigm(float x) { return 1.f / (1.f + expf(-x)); }

// ---------------- e_node / e_forw projection: warp per output ----------------
__global__ void eh_proj_kernel(const float* __restrict__ eh, const float* __restrict__ Wn,
                               const float* __restrict__ Wf, float* __restrict__ en,
                               float* __restrict__ ef) {
    int gw   = (blockIdx.x * blockDim.x + threadIdx.x) >> 5;
    int lane = threadIdx.x & 31;
    if (gw >= 2 * B_ * F_) return;
    int which = (gw >= B_ * F_);
    int rem   = which ? gw - B_ * F_ : gw;
    int b = rem >> 9, f = rem & 511;
    const float4* w4 = (const float4*)((which ? Wf : Wn) + (size_t)f * 1024);
    const float4* e4 = (const float4*)(eh + (size_t)b * 1024);
    float s = 0.f;
    for (int k = lane; k < 256; k += 32) {
        float4 a = w4[k], c = e4[k];
        s += a.x * c.x + a.y * c.y + a.z * c.z + a.w * c.w;
    }
    #pragma unroll
    for (int o = 16; o; o >>= 1) s += __shfl_down_sync(0xffffffffu, s, o);
    if (!lane) (which ? ef : en)[rem] = s;
}

// ---------------- dot of each (b,node) row with a per-batch vector ----------------
__global__ void dot_kernel(const float* __restrict__ X, const float* __restrict__ v,
                           float* __restrict__ out) {
    int gw   = (blockIdx.x * blockDim.x + threadIdx.x) >> 5;
    int lane = threadIdx.x & 31;
    if (gw >= B_ * NN) return;
    int b = gw / NN;
    const float4* x4 = (const float4*)(X + (size_t)gw * F_);
    const float4* v4 = (const float4*)(v + (size_t)b * F_);
    float s = 0.f;
    #pragma unroll
    for (int k = lane; k < 128; k += 32) {
        float4 a = x4[k], c = v4[k];
        s += a.x * c.x + a.y * c.y + a.z * c.z + a.w * c.w;
    }
    #pragma unroll
    for (int o = 16; o; o >>= 1) s += __shfl_down_sync(0xffffffffu, s, o);
    if (!lane) out[gw] = s;
}

// ---------------- windowed softmax attention -> feat2 ----------------
__global__ void feat2_kernel(const float* __restrict__ feat, const float* __restrict__ scores,
                             float* __restrict__ feat2) {
    int bi = blockIdx.x;           // = b*NN + i
    int b = bi / NN, i = bi % NN;
    int cnt = min(i + 3, NN - 1) - i + 1;
    float w[4];
    float mx = -1e30f;
    for (int j = 0; j < cnt; j++) { w[j] = scores[b * NN + i + j]; mx = fmaxf(mx, w[j]); }
    float s = 0.f;
    for (int j = 0; j < cnt; j++) { w[j] = expf(w[j] - mx); s += w[j]; }
    float inv = 1.f / s;
    const float4* base = (const float4*)(feat + (size_t)bi * F_);
    float4* o = (float4*)(feat2 + (size_t)bi * F_);
    for (int f = threadIdx.x; f < 128; f += 128) {
        float4 a = make_float4(0.f, 0.f, 0.f, 0.f);
        for (int j = 0; j < cnt; j++) {
            float4 v = base[j * 128 + f];
            a.x += w[j] * v.x; a.y += w[j] * v.y; a.z += w[j] * v.z; a.w += w[j] * v.w;
        }
        a.x *= inv; a.y *= inv; a.z *= inv; a.w *= inv;
        o[f] = a;
    }
}

// ---------------- pipelined SGEMM body ----------------
// C[M,N] = gather(A)[M,K] @ B[N,K]^T (+bias)
// mode 0: row m = A + m*K
// mode 1: b=m/cnt, node=nodeStart+m%cnt; row = A + b*bstride + node*K
// mode 2: like 1 but row = A[2*node+1] + A[2*node+2]  (children sum)
struct GP {
    const float* A; const float* Bm; const float* bias; float* C;
    int mode, M, N, K, nodeStart, cnt, bstride, gx;
};

__device__ __forceinline__ void gemm_dev(const GP& g, int tileM, int tileN,
                                         float (*As)[16][132], float (*Bs)[16][132]) {
    const int tid = threadIdx.x;
    const int tx = tid & 15, ty = tid >> 4;
    const int lr = tid >> 2;          // 0..63
    const int lc = (tid & 3) * 4;     // 0,4,8,12
    const int K = g.K;

    const float* ap[2]; const float* ap2[2]; bool av[2];
    #pragma unroll
    for (int p = 0; p < 2; p++) {
        int gm = tileM + lr + p * 64;
        av[p] = (gm < g.M);
        int gg = av[p] ? gm : 0;
        if (g.mode == 0) { ap[p] = g.A + (size_t)gg * K; ap2[p] = ap[p]; }
        else {
            int b = gg / g.cnt, node = g.nodeStart + gg % g.cnt;
            if (g.mode == 1) {
                ap[p] = g.A + (size_t)b * g.bstride + (size_t)node * K; ap2[p] = ap[p];
            } else {
                ap[p]  = g.A + (size_t)b * g.bstride + (size_t)(2 * node + 1) * K;
                ap2[p] = g.A + (size_t)b * g.bstride + (size_t)(2 * node + 2) * K;
            }
        }
    }
    const float* bp0 = g.Bm + (size_t)(tileN + lr) * K;
    const float* bp1 = g.Bm + (size_t)(tileN + lr + 64) * K;

    float4 ra[2], rb[2];
    // ---- prologue: load tile 0 ----
    #pragma unroll
    for (int p = 0; p < 2; p++) {
        float4 v = make_float4(0.f, 0.f, 0.f, 0.f);
        if (av[p]) {
            v = *(const float4*)(ap[p] + lc);
            if (g.mode == 2) {
                float4 w = *(const float4*)(ap2[p] + lc);
                v.x += w.x; v.y += w.y; v.z += w.z; v.w += w.w;
            }
        }
        ra[p] = v;
    }
    rb[0] = *(const float4*)(bp0 + lc);
    rb[1] = *(const float4*)(bp1 + lc);

    #pragma unroll
    for (int p = 0; p < 2; p++) {
        int m = lr + p * 64;
        As[0][lc + 0][m] = ra[p].x; As[0][lc + 1][m] = ra[p].y;
        As[0][lc + 2][m] = ra[p].z; As[0][lc + 3][m] = ra[p].w;
    }
    Bs[0][lc + 0][lr]      = rb[0].x; Bs[0][lc + 1][lr]      = rb[0].y;
    Bs[0][lc + 2][lr]      = rb[0].z; Bs[0][lc + 3][lr]      = rb[0].w;
    Bs[0][lc + 0][lr + 64] = rb[1].x; Bs[0][lc + 1][lr + 64] = rb[1].y;
    Bs[0][lc + 2][lr + 64] = rb[1].z; Bs[0][lc + 3][lr + 64] = rb[1].w;
    __syncthreads();

    float acc[8][8] = {};
    const int nt = K >> 4;
    int buf = 0;
    for (int t = 0; t < nt; t++) {
        if (t + 1 < nt) {
            int k0 = (t + 1) << 4;
            #pragma unroll
            for (int p = 0; p < 2; p++) {
                float4 v = make_float4(0.f, 0.f, 0.f, 0.f);
                if (av[p]) {
                    v = *(const float4*)(ap[p] + k0 + lc);
                    if (g.mode == 2) {
                        float4 w = *(const float4*)(ap2[p] + k0 + lc);
                        v.x += w.x; v.y += w.y; v.z += w.z; v.w += w.w;
                    }
                }
                ra[p] = v;
            }
            rb[0] = *(const float4*)(bp0 + k0 + lc);
            rb[1] = *(const float4*)(bp1 + k0 + lc);
        }
        #pragma unroll
        for (int kk = 0; kk < 16; kk++) {
            float4 t0 = *(const float4*)&As[buf][kk][ty * 8];
            float4 t1 = *(const float4*)&As[buf][kk][ty * 8 + 4];
            float4 u0 = *(const float4*)&Bs[buf][kk][tx * 8];
            float4 u1 = *(const float4*)&Bs[buf][kk][tx * 8 + 4];
            float a[8] = {t0.x, t0.y, t0.z, t0.w, t1.x, t1.y, t1.z, t1.w};
            float b[8] = {u0.x, u0.y, u0.z, u0.w, u1.x, u1.y, u1.z, u1.w};
            #pragma unroll
            for (int i = 0; i < 8; i++)
                #pragma unroll
                for (int j = 0; j < 8; j++)
                    acc[i][j] += a[i] * b[j];
        }
        if (t + 1 < nt) {
            int nb = buf ^ 1;
            #pragma unroll
            for (int p = 0; p < 2; p++) {
                int m = lr + p * 64;
                As[nb][lc + 0][m] = ra[p].x; As[nb][lc + 1][m] = ra[p].y;
                As[nb][lc + 2][m] = ra[p].z; As[nb][lc + 3][m] = ra[p].w;
            }
            Bs[nb][lc + 0][lr]      = rb[0].x; Bs[nb][lc + 1][lr]      = rb[0].y;
            Bs[nb][lc + 2][lr]      = rb[0].z; Bs[nb][lc + 3][lr]      = rb[0].w;
            Bs[nb][lc + 0][lr + 64] = rb[1].x; Bs[nb][lc + 1][lr + 64] = rb[1].y;
            Bs[nb][lc + 2][lr + 64] = rb[1].z; Bs[nb][lc + 3][lr + 64] = rb[1].w;
            __syncthreads();
            buf = nb;
        }
    }

    #pragma unroll
    for (int i = 0; i < 8; i++) {
        int gm = tileM + ty * 8 + i;
        if (gm >= g.M) continue;
        float* crow = g.C + (size_t)gm * g.N + tileN + tx * 8;
        float4 o0, o1;
        o0.x = acc[i][0]; o0.y = acc[i][1]; o0.z = acc[i][2]; o0.w = acc[i][3];
        o1.x = acc[i][4]; o1.y = acc[i][5]; o1.z = acc[i][6]; o1.w = acc[i][7];
        if (g.bias) {
            const float* bb = g.bias + tileN + tx * 8;
            o0.x += bb[0]; o0.y += bb[1]; o0.z += bb[2]; o0.w += bb[3];
            o1.x += bb[4]; o1.y += bb[5]; o1.z += bb[6]; o1.w += bb[7];
        }
        *(float4*)crow = o0;
        *(float4*)(crow + 4) = o1;
    }
}

// two independent GEMMs in one launch: blockIdx.z selects the parameter set
__global__ __launch_bounds__(256, 2)
void dual_gemm(GP g0, GP g1) {
    __shared__ float As[2][16][132];
    __shared__ float Bs[2][16][132];
    const GP& g = (blockIdx.z == 0) ? g0 : g1;
    int tileN = blockIdx.x * 128;
    int tileM = blockIdx.y * 128;
    if ((int)blockIdx.x >= g.gx || tileM >= g.M) return;
    gemm_dev(g, tileM, tileN, As, Bs);
}

// ---------------- leaves (order 0): nodes 255..510 ----------------
__global__ void leaf_kernel(const float* __restrict__ feiou, float* __restrict__ h,
                            float* __restrict__ c) {
    size_t idx = (size_t)blockIdx.x * blockDim.x + threadIdx.x;   // over B*256*128 float4s
    if (idx >= (size_t)B_ * 256 * 128) return;
    int f4 = (int)(idx & 127);
    size_t t = idx >> 7;
    int node = 255 + (int)(t % 256);
    int b = (int)(t / 256);
    size_t row = (size_t)b * NN + node;
    const float4* r = (const float4*)(feiou + row * F3);
    float4 ig = r[f4], og = r[128 + f4], ug = r[256 + f4];
    float4 cn, hn;
    cn.x = sigm(ig.x) * fmaxf(ug.x, 0.f); hn.x = sigm(og.x) * tanhf(cn.x);
    cn.y = sigm(ig.y) * fmaxf(ug.y, 0.f); hn.y = sigm(og.y) * tanhf(cn.y);
    cn.z = sigm(ig.z) * fmaxf(ug.z, 0.f); hn.z = sigm(og.z) * tanhf(cn.z);
    cn.w = sigm(ig.w) * fmaxf(ug.w, 0.f); hn.w = sigm(og.w) * tanhf(cn.w);
    ((float4*)(c + row * F_))[f4] = cn;
    ((float4*)(h + row * F_))[f4] = hn;
}

// ---------------- per-level combine / gate update ----------------
__global__ void combine_kernel(const float* __restrict__ iou_t, const float* __restrict__ f_t,
                               const float* __restrict__ feiou, const float* __restrict__ fefp,
                               float* __restrict__ h, float* __restrict__ c,
                               int start, int cnt) {
    size_t idx = (size_t)blockIdx.x * blockDim.x + threadIdx.x;   // over B*cnt*128 float4s
    if (idx >= (size_t)B_ * cnt * 128) return;
    int f4 = (int)(idx & 127);
    size_t t = idx >> 7;
    int q = (int)(t % cnt);
    int b = (int)(t / cnt);
    int p = start + q;
    size_t r    = (size_t)b * cnt + q;
    size_t prow = (size_t)b * NN + p;
    const float4* it = (const float4*)(iou_t + r * F3);
    const float4* fi = (const float4*)(feiou + prow * F3);
    float4 ig = it[f4],        og = it[128 + f4],  ug = it[256 + f4];
    float4 i2 = fi[f4],        o2 = fi[128 + f4],  u2 = fi[256 + f4];
    ig.x += i2.x; ig.y += i2.y; ig.z += i2.z; ig.w += i2.w;
    og.x += o2.x; og.y += o2.y; og.z += o2.z; og.w += o2.w;
    ug.x += u2.x; ug.y += u2.y; ug.z += u2.z; ug.w += u2.w;
    float4 fe = ((const float4*)(fefp + ((size_t)b * NP + p) * F_))[f4];
    size_t rf = ((size_t)b * 2 * cnt + 2 * q) * F_;
    float4 fl = ((const float4*)(f_t + rf))[f4];
    float4 fr = ((const float4*)(f_t + rf + F_))[f4];
    size_t cl = ((size_t)b * NN + 2 * p + 1) * F_;
    float4 cL = ((const float4*)(c + cl))[f4];
    float4 cR = ((const float4*)(c + cl + F_))[f4];
    float4 cn, hn;
    {
        float csum = sigm(fl.x + fe.x) * cL.x + sigm(fr.x + fe.x) * cR.x;
        cn.x = sigm(ig.x) * fmaxf(ug.x, 0.f) + csum; hn.x = sigm(og.x) * tanhf(cn.x);
        csum = sigm(fl.y + fe.y) * cL.y + sigm(fr.y + fe.y) * cR.y;
        cn.y = sigm(ig.y) * fmaxf(ug.y, 0.f) + csum; hn.y = sigm(og.y) * tanhf(cn.y);
        csum = sigm(fl.z + fe.z) * cL.z + sigm(fr.z + fe.z) * cR.z;
        cn.z = sigm(ig.z) * fmaxf(ug.z, 0.f) + csum; hn.z = sigm(og.z) * tanhf(cn.z);
        csum = sigm(fl.w + fe.w) * cL.w + sigm(fr.w + fe.w) * cR.w;
        cn.w = sigm(ig.w) * fmaxf(ug.w, 0.f) + csum; hn.w = sigm(og.w) * tanhf(cn.w);
    }
    ((float4*)(c + prow * F_))[f4] = cn;
    ((float4*)(h + prow * F_))[f4] = hn;
}

// ---------------- final: softmax over nodes, weighted sum of h ----------------
__global__ void final_kernel(const float* __restrict__ logits, const float* __restrict__ h,
                             float* __restrict__ out) {
    int b = blockIdx.x;
    int t = threadIdx.x;  // 512 threads; t is also the feature index
    __shared__ float sp[512];
    __shared__ float red[17];
    float l = (t < NN) ? logits[b * NN + t] : -1e30f;
    float m = l;
    #pragma unroll
    for (int o = 16; o; o >>= 1) m = fmaxf(m, __shfl_xor_sync(0xffffffffu, m, o));
    if ((t & 31) == 0) red[t >> 5] = m;
    __syncthreads();
    if (t == 0) {
        float mm = red[0];
        for (int i = 1; i < 16; i++) mm = fmaxf(mm, red[i]);
        red[16] = mm;
    }
    __syncthreads();
    float mx = red[16];
    float e = (t < NN) ? expf(l - mx) : 0.f;
    sp[t] = e;
    float s = e;
    #pragma unroll
    for (int o = 16; o; o >>= 1) s += __shfl_xor_sync(0xffffffffu, s, o);
    __syncthreads();
    if ((t & 31) == 0) red[t >> 5] = s;
    __syncthreads();
    if (t == 0) {
        float ss = 0.f;
        for (int i = 0; i < 16; i++) ss += red[i];
        red[16] = 1.f / ss;
    }
    __syncthreads();
    float inv = red[16];
    const float* hb = h + (size_t)b * NN * F_;
    float acc = 0.f;
    for (int i = 0; i < NN; i++) acc += sp[i] * hb[(size_t)i * F_ + t];
    out[b * F_ + t] = acc * inv;
}

// ---------------- launch ----------------
extern "C" void kernel_launch(void* const* d_in, const int* in_sizes, int n_in,
                              void* d_out, int out_size) {
    const float* features   = (const float*)d_in[0];
    const float* eh         = (const float*)d_in[5];
    const float* Wn         = (const float*)d_in[6];
    const float* Wf         = (const float*)d_in[7];
    const float* W_U_iou    = (const float*)d_in[8];
    const float* W_U_fe_iou = (const float*)d_in[9];
    const float* b_U_fe_iou = (const float*)d_in[10];
    const float* W_U_f      = (const float*)d_in[11];
    const float* W_U_fe_f   = (const float*)d_in[12];
    const float* b_U_fe_f   = (const float*)d_in[13];
    float* out = (float*)d_out;

    float *p_en, *p_ef, *p_sc, *p_lg, *p_feat2, *p_feiou, *p_fefp, *p_h, *p_c, *p_iou, *p_f;
    cudaGetSymbolAddress((void**)&p_en,    g_enode);
    cudaGetSymbolAddress((void**)&p_ef,    g_eforw);
    cudaGetSymbolAddress((void**)&p_sc,    g_scores);
    cudaGetSymbolAddress((void**)&p_lg,    g_logits);
    cudaGetSymbolAddress((void**)&p_feat2, g_feat2);
    cudaGetSymbolAddress((void**)&p_feiou, g_feiou);
    cudaGetSymbolAddress((void**)&p_fefp,  g_fefp);
    cudaGetSymbolAddress((void**)&p_h,     g_h);
    cudaGetSymbolAddress((void**)&p_c,     g_c);
    cudaGetSymbolAddress((void**)&p_iou,   g_iou_t);
    cudaGetSymbolAddress((void**)&p_f,     g_f_t);

    // 1) eh projections
    eh_proj_kernel<<<(2 * B_ * F_ * 32 + 255) / 256, 256>>>(eh, Wn, Wf, p_en, p_ef);
    // 2) attention scores + windowed softmax pooling
    dot_kernel<<<(B_ * NN * 32 + 255) / 256, 256>>>(features, p_en, p_sc);
    feat2_kernel<<<B_ * NN, 128>>>(features, p_sc, p_feat2);
    // 3) fe_iou (big GEMM) and per-parent fe_f — one dual launch, run concurrently
    {
        GP g0 = { p_feat2, W_U_fe_iou, b_U_fe_iou, p_feiou,
                  0, B_ * NN, F3, F_, 0, 1, 0, F3 / 128 };
        GP g1 = { p_feat2, W_U_fe_f, b_U_fe_f, p_fefp,
                  1, B_ * NP, F_, F_, 0, NP, NN * F_, F_ / 128 };
        dim3 grid(F3 / 128, (B_ * NN + 127) / 128, 2);
        dual_gemm<<<grid, 256>>>(g0, g1);
    }
    // 4) leaves
    leaf_kernel<<<(B_ * 256 * 128 + 255) / 256, 256>>>(p_feiou, p_h, p_c);
    // 5) levels bottom-up (n = 1..8)
    for (int n = 1; n <= 8; n++) {
        int cnt = 1 << (8 - n);     // parents at this level per batch
        int start = cnt - 1;        // first parent node id
        GP g0 = { p_h, W_U_iou, nullptr, p_iou,
                  2, B_ * cnt, F3, F_, start, cnt, NN * F_, F3 / 128 };
        GP g1 = { p_h, W_U_f, nullptr, p_f,
                  1, 2 * B_ * cnt, F_, F_, 2 * start + 1, 2 * cnt, NN * F_, F_ / 128 };
        int ymax = (2 * B_ * cnt + 127) / 128;
        int y0   = (B_ * cnt + 127) / 128;
        if (y0 > ymax) ymax = y0;
        dim3 grid(F3 / 128, ymax, 2);
        dual_gemm<<<grid, 256>>>(g0, g1);
        combine_kernel<<<(B_ * cnt * 128 + 255) / 256, 256>>>(p_iou, p_f, p_feiou, p_fefp,
                                                              p_h, p_c, start, cnt);
    }
    // 6) output pooling
    dot_kernel<<<(B_ * NN * 32 + 255) / 256, 256>>>(p_h, p_ef, p_lg);
    final_kernel<<<B_, F_>>>(p_lg, p_h, out);
}